// round 12
// baseline (speedup 1.0000x reference)
#include <cuda_runtime.h>
#include <math.h>
#include <stdint.h>

#define NN 8192
#define DD 64
#define SS 4096
#define BETA0 0.1f
#define BETA1 0.1f
#define EPS_C 1e-6f

#define CHUNK_F 2048                      // floats per chunk per row (8 KB)
#define CHUNK_B (CHUNK_F * 4)
#define NCHUNK (NN / CHUNK_F)             // 4 chunk-pairs
#define NBUF 2                            // 2 buffers -> 32 KB dyn smem -> 5 CTA/SM
#define DYN_SMEM (NBUF * 2 * CHUNK_B)     // 32 KB

#define SMOOTH_BLKS 128
#define HINGE_BLKS  512                   // 8 samples per block
// grid layout: [0, SS) = L_tr samples ; [SS, SS+128) = smooth ; [SS+128, SS+640) = hinge
#define TOTAL_BLKS (SS + SMOOTH_BLKS + HINGE_BLKS)

__device__ float g_Lsh;
__device__ float g_Ltr;
__device__ float g_sq;

__device__ __forceinline__ float softplus_stable(float x) {
    return fmaxf(x, 0.f) + log1pf(expf(-fabsf(x)));
}

// ---- TMA bulk-copy + mbarrier helpers ----
__device__ __forceinline__ void mbar_init(uint32_t mbar, uint32_t count) {
    asm volatile("mbarrier.init.shared.b64 [%0], %1;" :: "r"(mbar), "r"(count) : "memory");
}
__device__ __forceinline__ void mbar_expect_tx(uint32_t mbar, uint32_t bytes) {
    asm volatile("mbarrier.arrive.expect_tx.shared.b64 _, [%0], %1;"
                 :: "r"(mbar), "r"(bytes) : "memory");
}
__device__ __forceinline__ void bulk_g2s(uint32_t dst_smem, const void* src_gmem,
                                         uint32_t bytes, uint32_t mbar) {
    asm volatile(
        "cp.async.bulk.shared::cluster.global.mbarrier::complete_tx::bytes "
        "[%0], [%1], %2, [%3];"
        :: "r"(dst_smem), "l"(src_gmem), "r"(bytes), "r"(mbar) : "memory");
}
__device__ __forceinline__ void mbar_wait(uint32_t mbar, uint32_t parity) {
    asm volatile(
        "{\n\t"
        ".reg .pred P1;\n\t"
        "WAIT_LOOP_%=:\n\t"
        "mbarrier.try_wait.parity.acquire.cta.shared::cta.b64 P1, [%0], %1, 0x989680;\n\t"
        "@P1 bra.uni WAIT_DONE_%=;\n\t"
        "bra.uni WAIT_LOOP_%=;\n\t"
        "WAIT_DONE_%=:\n\t"
        "}"
        :: "r"(mbar), "r"(parity) : "memory");
}

// (1 - P) for one common neighbor; diag computed on the fly: theta_l . u_l
__device__ __forceinline__ float cn_term(float a, float b, int l,
                                         const float4* __restrict__ s_ui4,
                                         const float4* __restrict__ s_uj4,
                                         const float* __restrict__ theta,
                                         const float* __restrict__ emb_t) {
    const float4* th = (const float4*)(theta + (size_t)l * DD);
    const float4* ul = (const float4*)(emb_t + (size_t)l * DD);
    float tl = 0.f, ti = 0.f, tj = 0.f;
    #pragma unroll
    for (int q = 0; q < DD / 4; q++) {
        float4 t = __ldg(th + q);
        float4 u = __ldg(ul + q);
        float4 vi = s_ui4[q];
        float4 vj = s_uj4[q];
        tl += t.x * u.x  + t.y * u.y  + t.z * u.z  + t.w * u.w;
        ti += t.x * vi.x + t.y * vi.y + t.z * vi.z + t.w * vi.w;
        tj += t.x * vj.x + t.y * vj.y + t.z * vj.z + t.w * vj.w;
    }
    float dot = a * (tl - ti) + b * (tl - tj);
    if (dot < -100.f) return 1.f;
    float P = 1.f / (1.f + expf(-dot));
    return 1.f - P;
}

// ONE kernel: [0,SS) L_tr samples FIRST (start DMA asap), then smooth, then hinge.
__global__ void __launch_bounds__(256, 5) fused_kernel(
    const float* __restrict__ emb_t,
    const float* __restrict__ emb_prev,
    const float* __restrict__ theta,
    const float* __restrict__ adj,
    const int* __restrict__ j_idx,
    const int* __restrict__ k_idx,
    const int* __restrict__ negj_idx,
    const int* __restrict__ i_idx,
    const int* __restrict__ cond) {

    extern __shared__ __align__(16) float sbuf[];     // [NBUF][2][CHUNK_F] = 32 KB
    __shared__ alignas(8) unsigned long long smbar[NBUF];
    __shared__ float s_ui[DD];
    __shared__ float s_uj[DD];
    __shared__ float s_red[8];
    __shared__ float s_tik, s_tjk, s_dgk;

    int bid = blockIdx.x;
    int tid = threadIdx.x;
    int lane = tid & 31, w = tid >> 5;

    // ================= smooth: sum (emb_t - emb_prev)^2 =================
    if (bid >= SS && bid < SS + SMOOTH_BLKS) {
        int sb_id = bid - SS;
        const float4* et = (const float4*)emb_t;
        const float4* ep = (const float4*)emb_prev;
        const int TOT4 = NN * DD / 4;                 // 131072
        float ssum = 0.f;
        for (int q = sb_id * 256 + tid; q < TOT4; q += SMOOTH_BLKS * 256) {
            float4 a = __ldg(et + q);
            float4 b = __ldg(ep + q);
            float dx = a.x - b.x, dy = a.y - b.y, dz = a.z - b.z, dw = a.w - b.w;
            ssum += dx * dx + dy * dy + dz * dz + dw * dw;
        }
        #pragma unroll
        for (int o = 16; o; o >>= 1) ssum += __shfl_down_sync(0xffffffffu, ssum, o);
        if (lane == 0) s_red[w] = ssum;
        __syncthreads();
        if (tid == 0) {
            float t = s_red[0];
            #pragma unroll
            for (int x = 1; x < 8; x++) t += s_red[x];
            atomicAdd(&g_sq, t);
        }
        return;
    }
    // ================= triplet hinge =================
    if (bid >= SS + SMOOTH_BLKS) {
        int s = (bid - SS - SMOOTH_BLKS) * 8 + w;
        int j = j_idx[s], k = k_idx[s], nj = negj_idx[s];
        const float* uj = emb_t + (size_t)j  * DD;
        const float* uk = emb_t + (size_t)k  * DD;
        const float* un = emb_t + (size_t)nj * DD;
        float pos = 0.f, neg = 0.f;
        #pragma unroll
        for (int d = lane; d < DD; d += 32) {
            float a = uj[d] - uk[d]; pos += a * a;
            float b = un[d] - uk[d]; neg += b * b;
        }
        #pragma unroll
        for (int o = 16; o; o >>= 1) {
            pos += __shfl_down_sync(0xffffffffu, pos, o);
            neg += __shfl_down_sync(0xffffffffu, neg, o);
        }
        float h = pos - neg + 1.0f;
        if (lane == 0) s_red[w] = (h > 0.f) ? h : 0.f;
        __syncthreads();
        if (tid == 0) {
            float t = s_red[0];
            #pragma unroll
            for (int x = 1; x < 8; x++) t += s_red[x];
            if (t != 0.f) atomicAdd(&g_Lsh, t);
        }
        return;
    }
    // ================= L_tr: one block per sample =================
    {
        int s = bid;
        int c = __ldg(cond + s);
        if (c == -1) return;

        int i = __ldg(i_idx + s), j = __ldg(j_idx + s), k = __ldg(k_idx + s);

        if (tid < DD)          s_ui[tid]      = emb_t[(size_t)i * DD + tid];
        else if (tid < 2*DD)   s_uj[tid - DD] = emb_t[(size_t)j * DD + (tid - DD)];

        uint32_t mb0 = (uint32_t)__cvta_generic_to_shared(&smbar[0]);
        if (c == 1 && tid == 0) {
            #pragma unroll
            for (int cc = 0; cc < NBUF; ++cc) mbar_init(mb0 + 8 * cc, 1);
            asm volatile("fence.proxy.async.shared::cta;" ::: "memory");
        }
        __syncthreads();

        float prodL = 1.f;
        if (c == 1) {
            const float* ri = adj + (size_t)i * NN;
            const float* rj = adj + (size_t)j * NN;
            uint32_t sb = (uint32_t)__cvta_generic_to_shared(sbuf);

            if (tid == 0) {
                #pragma unroll
                for (int cc = 0; cc < NBUF; ++cc) {
                    uint32_t mb = mb0 + 8 * cc;
                    uint32_t dst = sb + (uint32_t)cc * 2 * CHUNK_B;
                    mbar_expect_tx(mb, 2 * CHUNK_B);
                    bulk_g2s(dst,           ri + (size_t)cc * CHUNK_F, CHUNK_B, mb);
                    bulk_g2s(dst + CHUNK_B, rj + (size_t)cc * CHUNK_F, CHUNK_B, mb);
                }
            }
            const float4* s_ui4 = (const float4*)s_ui;
            const float4* s_uj4 = (const float4*)s_uj;

            #pragma unroll
            for (int cc = 0; cc < NCHUNK; ++cc) {
                int buf = cc & (NBUF - 1);             // 0,1,0,1
                int ph  = cc >> 1;                     // 0,0,1,1
                mbar_wait(mb0 + 8 * buf, ph);
                const float4* A = (const float4*)(sbuf + (size_t)buf * 2 * CHUNK_F);
                const float4* B = (const float4*)(sbuf + (size_t)buf * 2 * CHUNK_F + CHUNK_F);
                #pragma unroll
                for (int it = 0; it < CHUNK_F / 4 / 256; ++it) {   // 2 iterations
                    int q = tid + it * 256;
                    float4 a = A[q];
                    float4 b = B[q];
                    int l0 = cc * CHUNK_F + q * 4;
                    if (a.x > 0.f && b.x > 0.f)
                        prodL *= cn_term(a.x, b.x, l0 + 0, s_ui4, s_uj4, theta, emb_t);
                    if (a.y > 0.f && b.y > 0.f)
                        prodL *= cn_term(a.y, b.y, l0 + 1, s_ui4, s_uj4, theta, emb_t);
                    if (a.z > 0.f && b.z > 0.f)
                        prodL *= cn_term(a.z, b.z, l0 + 2, s_ui4, s_uj4, theta, emb_t);
                    if (a.w > 0.f && b.w > 0.f)
                        prodL *= cn_term(a.w, b.w, l0 + 3, s_ui4, s_uj4, theta, emb_t);
                }
                if (cc + NBUF < NCHUNK) {
                    // this buffer fully consumed -> reissue chunk cc+2 into it
                    __syncthreads();
                    if (tid == 0) {
                        uint32_t mb = mb0 + 8 * buf;
                        uint32_t dst = sb + (uint32_t)buf * 2 * CHUNK_B;
                        mbar_expect_tx(mb, 2 * CHUNK_B);
                        bulk_g2s(dst,           ri + (size_t)(cc + NBUF) * CHUNK_F, CHUNK_B, mb);
                        bulk_g2s(dst + CHUNK_B, rj + (size_t)(cc + NBUF) * CHUNK_F, CHUNK_B, mb);
                    }
                }
            }
        }

        #pragma unroll
        for (int o = 16; o; o >>= 1)
            prodL *= __shfl_xor_sync(0xffffffffu, prodL, o);
        if (lane == 0) s_red[w] = prodL;
        __syncthreads();

        // warp0: theta_k.u_i ; warp1: theta_k.u_j ; warp2: theta_k.u_k
        if (w < 3) {
            const float* th = theta + (size_t)k * DD;
            const float* u = (w == 0) ? s_ui
                           : (w == 1) ? s_uj
                                      : emb_t + (size_t)k * DD;
            float acc = 0.f;
            #pragma unroll
            for (int d = lane; d < DD; d += 32) acc += u[d] * th[d];
            #pragma unroll
            for (int o = 16; o; o >>= 1)
                acc += __shfl_down_sync(0xffffffffu, acc, o);
            if (lane == 0) {
                if (w == 0) s_tik = acc;
                else if (w == 1) s_tjk = acc;
                else s_dgk = acc;
            }
        }
        __syncthreads();

        if (tid == 0) {
            float prodAll = s_red[0];
            #pragma unroll
            for (int x = 1; x < 8; x++) prodAll *= s_red[x];

            float a_ik = __ldg(adj + (size_t)i * NN + k);
            float a_jk = __ldg(adj + (size_t)j * NN + k);
            float dg = s_dgk;
            float dot_k = a_ik * (dg - s_tik) + a_jk * (dg - s_tjk);

            float ltr = softplus_stable(-dot_k);
            if (c == 1) {
                float C1 = 1.f - prodAll;
                float C0 = (dot_k < -100.f) ? 0.f : 1.f / (1.f + expf(-dot_k));
                ltr += 1.f - C0 / (C1 + EPS_C);
            } else {
                ltr += dot_k;
            }
            atomicAdd(&g_Ltr, ltr);
        }
    }
}

// reads accumulators, writes result, resets accumulators for the next replay
__global__ void final_kernel(float* __restrict__ out) {
    out[0] = g_Lsh + BETA0 * g_Ltr + BETA1 * ((float)SS) * g_sq;
    g_Lsh = 0.f; g_Ltr = 0.f; g_sq = 0.f;
}

extern "C" void kernel_launch(void* const* d_in, const int* in_sizes, int n_in,
                              void* d_out, int out_size) {
    const float* emb_t    = (const float*)d_in[0];
    const float* emb_prev = (const float*)d_in[1];
    const float* theta    = (const float*)d_in[2];
    const float* adj      = (const float*)d_in[3];
    const int*   j_idx    = (const int*)d_in[4];
    const int*   k_idx    = (const int*)d_in[5];
    const int*   negj_idx = (const int*)d_in[6];
    const int*   i_idx    = (const int*)d_in[7];
    const int*   cond     = (const int*)d_in[8];
    float* out = (float*)d_out;

    cudaFuncSetAttribute(fused_kernel,
                         cudaFuncAttributeMaxDynamicSharedMemorySize, DYN_SMEM);

    fused_kernel<<<TOTAL_BLKS, 256, DYN_SMEM>>>(
        emb_t, emb_prev, theta, adj, j_idx, k_idx, negj_idx, i_idx, cond);
    final_kernel<<<1, 1>>>(out);
}

// round 13
// speedup vs baseline: 1.2164x; 1.2164x over previous
#include <cuda_runtime.h>
#include <math.h>
#include <stdint.h>

#define NN 8192
#define DD 64
#define SS 4096
#define BETA0 0.1f
#define BETA1 0.1f
#define EPS_C 1e-6f

#define CHUNK_F 1024                      // floats per chunk per row (4 KB)
#define CHUNK_B (CHUNK_F * 4)
#define NCHUNK (NN / CHUNK_F)             // 8 chunk-pairs
#define NBUF 6                            // 6 buffers -> 48 KB dyn smem -> 4 CTA/SM
#define DYN_SMEM (NBUF * 2 * CHUNK_B)     // 48 KB

#define SMOOTH_BLKS 128
#define HINGE_BLKS  512                   // 8 samples per block
// grid layout: [0, SS) = L_tr samples ; [SS, SS+128) = smooth ; [SS+128, SS+640) = hinge
#define TOTAL_BLKS (SS + SMOOTH_BLKS + HINGE_BLKS)

__device__ float g_Lsh;
__device__ float g_Ltr;
__device__ float g_sq;

__device__ __forceinline__ float softplus_stable(float x) {
    return fmaxf(x, 0.f) + log1pf(expf(-fabsf(x)));
}

// ---- TMA bulk-copy + mbarrier helpers ----
__device__ __forceinline__ void mbar_init(uint32_t mbar, uint32_t count) {
    asm volatile("mbarrier.init.shared.b64 [%0], %1;" :: "r"(mbar), "r"(count) : "memory");
}
__device__ __forceinline__ void mbar_expect_tx(uint32_t mbar, uint32_t bytes) {
    asm volatile("mbarrier.arrive.expect_tx.shared.b64 _, [%0], %1;"
                 :: "r"(mbar), "r"(bytes) : "memory");
}
__device__ __forceinline__ void bulk_g2s(uint32_t dst_smem, const void* src_gmem,
                                         uint32_t bytes, uint32_t mbar) {
    asm volatile(
        "cp.async.bulk.shared::cluster.global.mbarrier::complete_tx::bytes "
        "[%0], [%1], %2, [%3];"
        :: "r"(dst_smem), "l"(src_gmem), "r"(bytes), "r"(mbar) : "memory");
}
__device__ __forceinline__ void mbar_wait(uint32_t mbar, uint32_t parity) {
    asm volatile(
        "{\n\t"
        ".reg .pred P1;\n\t"
        "WAIT_LOOP_%=:\n\t"
        "mbarrier.try_wait.parity.acquire.cta.shared::cta.b64 P1, [%0], %1, 0x989680;\n\t"
        "@P1 bra.uni WAIT_DONE_%=;\n\t"
        "bra.uni WAIT_LOOP_%=;\n\t"
        "WAIT_DONE_%=:\n\t"
        "}"
        :: "r"(mbar), "r"(parity) : "memory");
}

// (1 - P) for one common neighbor; diag computed on the fly: theta_l . u_l
__device__ __forceinline__ float cn_term(float a, float b, int l,
                                         const float4* __restrict__ s_ui4,
                                         const float4* __restrict__ s_uj4,
                                         const float* __restrict__ theta,
                                         const float* __restrict__ emb_t) {
    const float4* th = (const float4*)(theta + (size_t)l * DD);
    const float4* ul = (const float4*)(emb_t + (size_t)l * DD);
    float tl = 0.f, ti = 0.f, tj = 0.f;
    #pragma unroll
    for (int q = 0; q < DD / 4; q++) {
        float4 t = __ldg(th + q);
        float4 u = __ldg(ul + q);
        float4 vi = s_ui4[q];
        float4 vj = s_uj4[q];
        tl += t.x * u.x  + t.y * u.y  + t.z * u.z  + t.w * u.w;
        ti += t.x * vi.x + t.y * vi.y + t.z * vi.z + t.w * vi.w;
        tj += t.x * vj.x + t.y * vj.y + t.z * vj.z + t.w * vj.w;
    }
    float dot = a * (tl - ti) + b * (tl - tj);
    if (dot < -100.f) return 1.f;
    float P = 1.f / (1.f + expf(-dot));
    return 1.f - P;
}

// ONE kernel: [0,SS) L_tr samples FIRST (start DMA asap), then smooth, then hinge.
__global__ void __launch_bounds__(256) fused_kernel(
    const float* __restrict__ emb_t,
    const float* __restrict__ emb_prev,
    const float* __restrict__ theta,
    const float* __restrict__ adj,
    const int* __restrict__ j_idx,
    const int* __restrict__ k_idx,
    const int* __restrict__ negj_idx,
    const int* __restrict__ i_idx,
    const int* __restrict__ cond) {

    extern __shared__ __align__(16) float sbuf[];     // [NBUF][2][CHUNK_F] = 48 KB
    __shared__ alignas(8) unsigned long long smbar[NBUF];
    __shared__ float s_ui[DD];
    __shared__ float s_uj[DD];
    __shared__ float s_red[8];
    __shared__ float s_tik, s_tjk, s_dgk;

    int bid = blockIdx.x;
    int tid = threadIdx.x;
    int lane = tid & 31, w = tid >> 5;

    // ================= smooth: sum (emb_t - emb_prev)^2 =================
    if (bid >= SS && bid < SS + SMOOTH_BLKS) {
        int sb_id = bid - SS;
        const float4* et = (const float4*)emb_t;
        const float4* ep = (const float4*)emb_prev;
        const int TOT4 = NN * DD / 4;                 // 131072
        float ssum = 0.f;
        for (int q = sb_id * 256 + tid; q < TOT4; q += SMOOTH_BLKS * 256) {
            float4 a = __ldg(et + q);
            float4 b = __ldg(ep + q);
            float dx = a.x - b.x, dy = a.y - b.y, dz = a.z - b.z, dw = a.w - b.w;
            ssum += dx * dx + dy * dy + dz * dz + dw * dw;
        }
        #pragma unroll
        for (int o = 16; o; o >>= 1) ssum += __shfl_down_sync(0xffffffffu, ssum, o);
        if (lane == 0) s_red[w] = ssum;
        __syncthreads();
        if (tid == 0) {
            float t = s_red[0];
            #pragma unroll
            for (int x = 1; x < 8; x++) t += s_red[x];
            atomicAdd(&g_sq, t);
        }
        return;
    }
    // ================= triplet hinge =================
    if (bid >= SS + SMOOTH_BLKS) {
        int s = (bid - SS - SMOOTH_BLKS) * 8 + w;
        int j = j_idx[s], k = k_idx[s], nj = negj_idx[s];
        const float* uj = emb_t + (size_t)j  * DD;
        const float* uk = emb_t + (size_t)k  * DD;
        const float* un = emb_t + (size_t)nj * DD;
        float pos = 0.f, neg = 0.f;
        #pragma unroll
        for (int d = lane; d < DD; d += 32) {
            float a = uj[d] - uk[d]; pos += a * a;
            float b = un[d] - uk[d]; neg += b * b;
        }
        #pragma unroll
        for (int o = 16; o; o >>= 1) {
            pos += __shfl_down_sync(0xffffffffu, pos, o);
            neg += __shfl_down_sync(0xffffffffu, neg, o);
        }
        float h = pos - neg + 1.0f;
        if (lane == 0) s_red[w] = (h > 0.f) ? h : 0.f;
        __syncthreads();
        if (tid == 0) {
            float t = s_red[0];
            #pragma unroll
            for (int x = 1; x < 8; x++) t += s_red[x];
            if (t != 0.f) atomicAdd(&g_Lsh, t);
        }
        return;
    }
    // ================= L_tr: one block per sample =================
    {
        int s = bid;
        int c = __ldg(cond + s);
        if (c == -1) return;

        int i = __ldg(i_idx + s), j = __ldg(j_idx + s), k = __ldg(k_idx + s);

        if (tid < DD)          s_ui[tid]      = emb_t[(size_t)i * DD + tid];
        else if (tid < 2*DD)   s_uj[tid - DD] = emb_t[(size_t)j * DD + (tid - DD)];

        uint32_t mb0 = (uint32_t)__cvta_generic_to_shared(&smbar[0]);
        if (c == 1 && tid == 0) {
            #pragma unroll
            for (int cc = 0; cc < NBUF; ++cc) mbar_init(mb0 + 8 * cc, 1);
            asm volatile("fence.proxy.async.shared::cta;" ::: "memory");
        }
        __syncthreads();

        float prodL = 1.f;
        if (c == 1) {
            const float* ri = adj + (size_t)i * NN;
            const float* rj = adj + (size_t)j * NN;
            uint32_t sb = (uint32_t)__cvta_generic_to_shared(sbuf);

            if (tid == 0) {
                #pragma unroll
                for (int cc = 0; cc < NBUF; ++cc) {
                    uint32_t mb = mb0 + 8 * cc;
                    uint32_t dst = sb + (uint32_t)cc * 2 * CHUNK_B;
                    mbar_expect_tx(mb, 2 * CHUNK_B);
                    bulk_g2s(dst,           ri + (size_t)cc * CHUNK_F, CHUNK_B, mb);
                    bulk_g2s(dst + CHUNK_B, rj + (size_t)cc * CHUNK_F, CHUNK_B, mb);
                }
            }
            const float4* s_ui4 = (const float4*)s_ui;
            const float4* s_uj4 = (const float4*)s_uj;

            #pragma unroll
            for (int cc = 0; cc < NCHUNK; ++cc) {
                int buf = cc % NBUF;                   // 0..5,0,1
                int ph  = cc / NBUF;                   // 0 x6, 1 x2
                mbar_wait(mb0 + 8 * buf, ph);
                const float4* A = (const float4*)(sbuf + (size_t)buf * 2 * CHUNK_F);
                const float4* B = (const float4*)(sbuf + (size_t)buf * 2 * CHUNK_F + CHUNK_F);
                {
                    int q = tid;                        // CHUNK_F/4 == 256 == blockDim
                    float4 a = A[q];
                    float4 b = B[q];
                    int l0 = cc * CHUNK_F + q * 4;
                    if (a.x > 0.f && b.x > 0.f)
                        prodL *= cn_term(a.x, b.x, l0 + 0, s_ui4, s_uj4, theta, emb_t);
                    if (a.y > 0.f && b.y > 0.f)
                        prodL *= cn_term(a.y, b.y, l0 + 1, s_ui4, s_uj4, theta, emb_t);
                    if (a.z > 0.f && b.z > 0.f)
                        prodL *= cn_term(a.z, b.z, l0 + 2, s_ui4, s_uj4, theta, emb_t);
                    if (a.w > 0.f && b.w > 0.f)
                        prodL *= cn_term(a.w, b.w, l0 + 3, s_ui4, s_uj4, theta, emb_t);
                }
                if (cc + NBUF < NCHUNK) {
                    // this buffer fully consumed -> reissue chunk cc+NBUF into it
                    __syncthreads();
                    if (tid == 0) {
                        uint32_t mb = mb0 + 8 * buf;
                        uint32_t dst = sb + (uint32_t)buf * 2 * CHUNK_B;
                        mbar_expect_tx(mb, 2 * CHUNK_B);
                        bulk_g2s(dst,           ri + (size_t)(cc + NBUF) * CHUNK_F, CHUNK_B, mb);
                        bulk_g2s(dst + CHUNK_B, rj + (size_t)(cc + NBUF) * CHUNK_F, CHUNK_B, mb);
                    }
                }
            }
        }

        #pragma unroll
        for (int o = 16; o; o >>= 1)
            prodL *= __shfl_xor_sync(0xffffffffu, prodL, o);
        if (lane == 0) s_red[w] = prodL;
        __syncthreads();

        // warp0: theta_k.u_i ; warp1: theta_k.u_j ; warp2: theta_k.u_k
        if (w < 3) {
            const float* th = theta + (size_t)k * DD;
            const float* u = (w == 0) ? s_ui
                           : (w == 1) ? s_uj
                                      : emb_t + (size_t)k * DD;
            float acc = 0.f;
            #pragma unroll
            for (int d = lane; d < DD; d += 32) acc += u[d] * th[d];
            #pragma unroll
            for (int o = 16; o; o >>= 1)
                acc += __shfl_down_sync(0xffffffffu, acc, o);
            if (lane == 0) {
                if (w == 0) s_tik = acc;
                else if (w == 1) s_tjk = acc;
                else s_dgk = acc;
            }
        }
        __syncthreads();

        if (tid == 0) {
            float prodAll = s_red[0];
            #pragma unroll
            for (int x = 1; x < 8; x++) prodAll *= s_red[x];

            float a_ik = __ldg(adj + (size_t)i * NN + k);
            float a_jk = __ldg(adj + (size_t)j * NN + k);
            float dg = s_dgk;
            float dot_k = a_ik * (dg - s_tik) + a_jk * (dg - s_tjk);

            float ltr = softplus_stable(-dot_k);
            if (c == 1) {
                float C1 = 1.f - prodAll;
                float C0 = (dot_k < -100.f) ? 0.f : 1.f / (1.f + expf(-dot_k));
                ltr += 1.f - C0 / (C1 + EPS_C);
            } else {
                ltr += dot_k;
            }
            atomicAdd(&g_Ltr, ltr);
        }
    }
}

// reads accumulators, writes result, resets accumulators for the next replay
__global__ void final_kernel(float* __restrict__ out) {
    out[0] = g_Lsh + BETA0 * g_Ltr + BETA1 * ((float)SS) * g_sq;
    g_Lsh = 0.f; g_Ltr = 0.f; g_sq = 0.f;
}

extern "C" void kernel_launch(void* const* d_in, const int* in_sizes, int n_in,
                              void* d_out, int out_size) {
    const float* emb_t    = (const float*)d_in[0];
    const float* emb_prev = (const float*)d_in[1];
    const float* theta    = (const float*)d_in[2];
    const float* adj      = (const float*)d_in[3];
    const int*   j_idx    = (const int*)d_in[4];
    const int*   k_idx    = (const int*)d_in[5];
    const int*   negj_idx = (const int*)d_in[6];
    const int*   i_idx    = (const int*)d_in[7];
    const int*   cond     = (const int*)d_in[8];
    float* out = (float*)d_out;

    cudaFuncSetAttribute(fused_kernel,
                         cudaFuncAttributeMaxDynamicSharedMemorySize, DYN_SMEM);

    fused_kernel<<<TOTAL_BLKS, 256, DYN_SMEM>>>(
        emb_t, emb_prev, theta, adj, j_idx, k_idx, negj_idx, i_idx, cond);
    final_kernel<<<1, 1>>>(out);
}

// round 14
// speedup vs baseline: 1.2792x; 1.0517x over previous
#include <cuda_runtime.h>
#include <math.h>
#include <stdint.h>

#define NN 8192
#define DD 64
#define SS 4096
#define BETA0 0.1f
#define BETA1 0.1f
#define EPS_C 1e-6f

#define THREADS 128                       // one sample per 128-thread block
#define CHUNK_F 1024                      // floats per chunk per row (4 KB)
#define CHUNK_B (CHUNK_F * 4)
#define NCHUNK (NN / CHUNK_F)             // 8 chunk-pairs
#define NBUF 4                            // 4 buffers -> 32 KB dyn smem -> ~6 CTA/SM
#define DYN_SMEM (NBUF * 2 * CHUNK_B)     // 32 KB

#define SMOOTH_BLKS 128
#define HINGE_BLKS  1024                  // 4 samples per 128-thr block
// grid layout: [0, SS) = L_tr samples ; [SS, SS+128) = smooth ; then hinge
#define TOTAL_BLKS (SS + SMOOTH_BLKS + HINGE_BLKS)

__device__ float g_Lsh;
__device__ float g_Ltr;
__device__ float g_sq;

__device__ __forceinline__ float softplus_stable(float x) {
    return fmaxf(x, 0.f) + log1pf(expf(-fabsf(x)));
}

// ---- TMA bulk-copy + mbarrier helpers ----
__device__ __forceinline__ void mbar_init(uint32_t mbar, uint32_t count) {
    asm volatile("mbarrier.init.shared.b64 [%0], %1;" :: "r"(mbar), "r"(count) : "memory");
}
__device__ __forceinline__ void mbar_expect_tx(uint32_t mbar, uint32_t bytes) {
    asm volatile("mbarrier.arrive.expect_tx.shared.b64 _, [%0], %1;"
                 :: "r"(mbar), "r"(bytes) : "memory");
}
__device__ __forceinline__ void bulk_g2s(uint32_t dst_smem, const void* src_gmem,
                                         uint32_t bytes, uint32_t mbar) {
    asm volatile(
        "cp.async.bulk.shared::cluster.global.mbarrier::complete_tx::bytes "
        "[%0], [%1], %2, [%3];"
        :: "r"(dst_smem), "l"(src_gmem), "r"(bytes), "r"(mbar) : "memory");
}
__device__ __forceinline__ void mbar_wait(uint32_t mbar, uint32_t parity) {
    asm volatile(
        "{\n\t"
        ".reg .pred P1;\n\t"
        "WAIT_LOOP_%=:\n\t"
        "mbarrier.try_wait.parity.acquire.cta.shared::cta.b64 P1, [%0], %1, 0x989680;\n\t"
        "@P1 bra.uni WAIT_DONE_%=;\n\t"
        "bra.uni WAIT_LOOP_%=;\n\t"
        "WAIT_DONE_%=:\n\t"
        "}"
        :: "r"(mbar), "r"(parity) : "memory");
}

// (1 - P) for one common neighbor; diag computed on the fly: theta_l . u_l
__device__ __forceinline__ float cn_term(float a, float b, int l,
                                         const float4* __restrict__ s_ui4,
                                         const float4* __restrict__ s_uj4,
                                         const float* __restrict__ theta,
                                         const float* __restrict__ emb_t) {
    const float4* th = (const float4*)(theta + (size_t)l * DD);
    const float4* ul = (const float4*)(emb_t + (size_t)l * DD);
    float tl = 0.f, ti = 0.f, tj = 0.f;
    #pragma unroll
    for (int q = 0; q < DD / 4; q++) {
        float4 t = __ldg(th + q);
        float4 u = __ldg(ul + q);
        float4 vi = s_ui4[q];
        float4 vj = s_uj4[q];
        tl += t.x * u.x  + t.y * u.y  + t.z * u.z  + t.w * u.w;
        ti += t.x * vi.x + t.y * vi.y + t.z * vi.z + t.w * vi.w;
        tj += t.x * vj.x + t.y * vj.y + t.z * vj.z + t.w * vj.w;
    }
    float dot = a * (tl - ti) + b * (tl - tj);
    if (dot < -100.f) return 1.f;
    float P = 1.f / (1.f + expf(-dot));
    return 1.f - P;
}

// ONE kernel: [0,SS) L_tr samples FIRST (start DMA asap), then smooth, then hinge.
__global__ void __launch_bounds__(THREADS) fused_kernel(
    const float* __restrict__ emb_t,
    const float* __restrict__ emb_prev,
    const float* __restrict__ theta,
    const float* __restrict__ adj,
    const int* __restrict__ j_idx,
    const int* __restrict__ k_idx,
    const int* __restrict__ negj_idx,
    const int* __restrict__ i_idx,
    const int* __restrict__ cond) {

    extern __shared__ __align__(16) float sbuf[];     // [NBUF][2][CHUNK_F] = 32 KB
    __shared__ alignas(8) unsigned long long smbar[NBUF];
    __shared__ float s_ui[DD];
    __shared__ float s_uj[DD];
    __shared__ float s_red[4];
    __shared__ float s_tik, s_tjk, s_dgk;

    int bid = blockIdx.x;
    int tid = threadIdx.x;
    int lane = tid & 31, w = tid >> 5;

    // ================= smooth: sum (emb_t - emb_prev)^2 =================
    if (bid >= SS && bid < SS + SMOOTH_BLKS) {
        int sb_id = bid - SS;
        const float4* et = (const float4*)emb_t;
        const float4* ep = (const float4*)emb_prev;
        const int TOT4 = NN * DD / 4;                 // 131072
        float ssum = 0.f;
        for (int q = sb_id * THREADS + tid; q < TOT4; q += SMOOTH_BLKS * THREADS) {
            float4 a = __ldg(et + q);
            float4 b = __ldg(ep + q);
            float dx = a.x - b.x, dy = a.y - b.y, dz = a.z - b.z, dw = a.w - b.w;
            ssum += dx * dx + dy * dy + dz * dz + dw * dw;
        }
        #pragma unroll
        for (int o = 16; o; o >>= 1) ssum += __shfl_down_sync(0xffffffffu, ssum, o);
        if (lane == 0) s_red[w] = ssum;
        __syncthreads();
        if (tid == 0) {
            float t = s_red[0] + s_red[1] + s_red[2] + s_red[3];
            atomicAdd(&g_sq, t);
        }
        return;
    }
    // ================= triplet hinge =================
    if (bid >= SS + SMOOTH_BLKS) {
        int s = (bid - SS - SMOOTH_BLKS) * 4 + w;
        int j = j_idx[s], k = k_idx[s], nj = negj_idx[s];
        const float* uj = emb_t + (size_t)j  * DD;
        const float* uk = emb_t + (size_t)k  * DD;
        const float* un = emb_t + (size_t)nj * DD;
        float pos = 0.f, neg = 0.f;
        #pragma unroll
        for (int d = lane; d < DD; d += 32) {
            float a = uj[d] - uk[d]; pos += a * a;
            float b = un[d] - uk[d]; neg += b * b;
        }
        #pragma unroll
        for (int o = 16; o; o >>= 1) {
            pos += __shfl_down_sync(0xffffffffu, pos, o);
            neg += __shfl_down_sync(0xffffffffu, neg, o);
        }
        float h = pos - neg + 1.0f;
        if (lane == 0) s_red[w] = (h > 0.f) ? h : 0.f;
        __syncthreads();
        if (tid == 0) {
            float t = s_red[0] + s_red[1] + s_red[2] + s_red[3];
            if (t != 0.f) atomicAdd(&g_Lsh, t);
        }
        return;
    }
    // ================= L_tr: one block per sample =================
    {
        int s = bid;
        int c = __ldg(cond + s);
        if (c == -1) return;

        int i = __ldg(i_idx + s), j = __ldg(j_idx + s), k = __ldg(k_idx + s);

        if (tid < DD)  s_ui[tid]      = emb_t[(size_t)i * DD + tid];
        else           s_uj[tid - DD] = emb_t[(size_t)j * DD + (tid - DD)];

        uint32_t mb0 = (uint32_t)__cvta_generic_to_shared(&smbar[0]);
        if (c == 1 && tid == 0) {
            #pragma unroll
            for (int cc = 0; cc < NBUF; ++cc) mbar_init(mb0 + 8 * cc, 1);
            asm volatile("fence.proxy.async.shared::cta;" ::: "memory");
        }
        __syncthreads();

        float prodL = 1.f;
        if (c == 1) {
            const float* ri = adj + (size_t)i * NN;
            const float* rj = adj + (size_t)j * NN;
            uint32_t sb = (uint32_t)__cvta_generic_to_shared(sbuf);

            if (tid == 0) {
                #pragma unroll
                for (int cc = 0; cc < NBUF; ++cc) {
                    uint32_t mb = mb0 + 8 * cc;
                    uint32_t dst = sb + (uint32_t)cc * 2 * CHUNK_B;
                    mbar_expect_tx(mb, 2 * CHUNK_B);
                    bulk_g2s(dst,           ri + (size_t)cc * CHUNK_F, CHUNK_B, mb);
                    bulk_g2s(dst + CHUNK_B, rj + (size_t)cc * CHUNK_F, CHUNK_B, mb);
                }
            }
            const float4* s_ui4 = (const float4*)s_ui;
            const float4* s_uj4 = (const float4*)s_uj;

            #pragma unroll
            for (int cc = 0; cc < NCHUNK; ++cc) {
                int buf = cc % NBUF;                   // 0..3,0..3
                int ph  = cc / NBUF;                   // 0 x4, 1 x4
                mbar_wait(mb0 + 8 * buf, ph);
                const float4* A = (const float4*)(sbuf + (size_t)buf * 2 * CHUNK_F);
                const float4* B = (const float4*)(sbuf + (size_t)buf * 2 * CHUNK_F + CHUNK_F);
                #pragma unroll
                for (int it = 0; it < CHUNK_F / 4 / THREADS; ++it) {   // 2 iterations
                    int q = tid + it * THREADS;
                    float4 a = A[q];
                    float4 b = B[q];
                    int l0 = cc * CHUNK_F + q * 4;
                    if (a.x > 0.f && b.x > 0.f)
                        prodL *= cn_term(a.x, b.x, l0 + 0, s_ui4, s_uj4, theta, emb_t);
                    if (a.y > 0.f && b.y > 0.f)
                        prodL *= cn_term(a.y, b.y, l0 + 1, s_ui4, s_uj4, theta, emb_t);
                    if (a.z > 0.f && b.z > 0.f)
                        prodL *= cn_term(a.z, b.z, l0 + 2, s_ui4, s_uj4, theta, emb_t);
                    if (a.w > 0.f && b.w > 0.f)
                        prodL *= cn_term(a.w, b.w, l0 + 3, s_ui4, s_uj4, theta, emb_t);
                }
                if (cc + NBUF < NCHUNK) {
                    // this buffer fully consumed -> reissue chunk cc+NBUF into it
                    __syncthreads();
                    if (tid == 0) {
                        uint32_t mb = mb0 + 8 * buf;
                        uint32_t dst = sb + (uint32_t)buf * 2 * CHUNK_B;
                        mbar_expect_tx(mb, 2 * CHUNK_B);
                        bulk_g2s(dst,           ri + (size_t)(cc + NBUF) * CHUNK_F, CHUNK_B, mb);
                        bulk_g2s(dst + CHUNK_B, rj + (size_t)(cc + NBUF) * CHUNK_F, CHUNK_B, mb);
                    }
                }
            }
        }

        #pragma unroll
        for (int o = 16; o; o >>= 1)
            prodL *= __shfl_xor_sync(0xffffffffu, prodL, o);
        if (lane == 0) s_red[w] = prodL;
        __syncthreads();

        // warp0: theta_k.u_i ; warp1: theta_k.u_j ; warp2: theta_k.u_k
        if (w < 3) {
            const float* th = theta + (size_t)k * DD;
            const float* u = (w == 0) ? s_ui
                           : (w == 1) ? s_uj
                                      : emb_t + (size_t)k * DD;
            float acc = 0.f;
            #pragma unroll
            for (int d = lane; d < DD; d += 32) acc += u[d] * th[d];
            #pragma unroll
            for (int o = 16; o; o >>= 1)
                acc += __shfl_down_sync(0xffffffffu, acc, o);
            if (lane == 0) {
                if (w == 0) s_tik = acc;
                else if (w == 1) s_tjk = acc;
                else s_dgk = acc;
            }
        }
        __syncthreads();

        if (tid == 0) {
            float prodAll = s_red[0] * s_red[1] * s_red[2] * s_red[3];

            float a_ik = __ldg(adj + (size_t)i * NN + k);
            float a_jk = __ldg(adj + (size_t)j * NN + k);
            float dg = s_dgk;
            float dot_k = a_ik * (dg - s_tik) + a_jk * (dg - s_tjk);

            float ltr = softplus_stable(-dot_k);
            if (c == 1) {
                float C1 = 1.f - prodAll;
                float C0 = (dot_k < -100.f) ? 0.f : 1.f / (1.f + expf(-dot_k));
                ltr += 1.f - C0 / (C1 + EPS_C);
            } else {
                ltr += dot_k;
            }
            atomicAdd(&g_Ltr, ltr);
        }
    }
}

// reads accumulators, writes result, resets accumulators for the next replay
__global__ void final_kernel(float* __restrict__ out) {
    out[0] = g_Lsh + BETA0 * g_Ltr + BETA1 * ((float)SS) * g_sq;
    g_Lsh = 0.f; g_Ltr = 0.f; g_sq = 0.f;
}

extern "C" void kernel_launch(void* const* d_in, const int* in_sizes, int n_in,
                              void* d_out, int out_size) {
    const float* emb_t    = (const float*)d_in[0];
    const float* emb_prev = (const float*)d_in[1];
    const float* theta    = (const float*)d_in[2];
    const float* adj      = (const float*)d_in[3];
    const int*   j_idx    = (const int*)d_in[4];
    const int*   k_idx    = (const int*)d_in[5];
    const int*   negj_idx = (const int*)d_in[6];
    const int*   i_idx    = (const int*)d_in[7];
    const int*   cond     = (const int*)d_in[8];
    float* out = (float*)d_out;

    cudaFuncSetAttribute(fused_kernel,
                         cudaFuncAttributeMaxDynamicSharedMemorySize, DYN_SMEM);

    fused_kernel<<<TOTAL_BLKS, THREADS, DYN_SMEM>>>(
        emb_t, emb_prev, theta, adj, j_idx, k_idx, negj_idx, i_idx, cond);
    final_kernel<<<1, 1>>>(out);
}

// round 15
// speedup vs baseline: 1.3131x; 1.0265x over previous
#include <cuda_runtime.h>
#include <math.h>
#include <stdint.h>

#define NN 8192
#define DD 64
#define SS 4096
#define BETA0 0.1f
#define BETA1 0.1f
#define EPS_C 1e-6f

#define THREADS 128                       // one sample per 128-thread block
#define CHUNK_F 1024                      // floats per chunk per row (4 KB)
#define CHUNK_B (CHUNK_F * 4)
#define NCHUNK (NN / CHUNK_F)             // 8 chunk-pairs
#define NBUF 3                            // 3 buffers -> 24 KB dyn smem -> ~8 CTA/SM
#define DYN_SMEM (NBUF * 2 * CHUNK_B)     // 24 KB

#define SMOOTH_BLKS 128
#define HINGE_BLKS  1024                  // 4 samples per 128-thr block
// grid layout: [0, SS) = L_tr samples ; [SS, SS+128) = smooth ; then hinge
#define TOTAL_BLKS (SS + SMOOTH_BLKS + HINGE_BLKS)

__device__ float g_Lsh;
__device__ float g_Ltr;
__device__ float g_sq;

__device__ __forceinline__ float softplus_stable(float x) {
    return fmaxf(x, 0.f) + log1pf(expf(-fabsf(x)));
}

// ---- TMA bulk-copy + mbarrier helpers ----
__device__ __forceinline__ void mbar_init(uint32_t mbar, uint32_t count) {
    asm volatile("mbarrier.init.shared.b64 [%0], %1;" :: "r"(mbar), "r"(count) : "memory");
}
__device__ __forceinline__ void mbar_expect_tx(uint32_t mbar, uint32_t bytes) {
    asm volatile("mbarrier.arrive.expect_tx.shared.b64 _, [%0], %1;"
                 :: "r"(mbar), "r"(bytes) : "memory");
}
__device__ __forceinline__ void bulk_g2s(uint32_t dst_smem, const void* src_gmem,
                                         uint32_t bytes, uint32_t mbar) {
    asm volatile(
        "cp.async.bulk.shared::cluster.global.mbarrier::complete_tx::bytes "
        "[%0], [%1], %2, [%3];"
        :: "r"(dst_smem), "l"(src_gmem), "r"(bytes), "r"(mbar) : "memory");
}
__device__ __forceinline__ void mbar_wait(uint32_t mbar, uint32_t parity) {
    asm volatile(
        "{\n\t"
        ".reg .pred P1;\n\t"
        "WAIT_LOOP_%=:\n\t"
        "mbarrier.try_wait.parity.acquire.cta.shared::cta.b64 P1, [%0], %1, 0x989680;\n\t"
        "@P1 bra.uni WAIT_DONE_%=;\n\t"
        "bra.uni WAIT_LOOP_%=;\n\t"
        "WAIT_DONE_%=:\n\t"
        "}"
        :: "r"(mbar), "r"(parity) : "memory");
}

// (1 - P) for one common neighbor; diag computed on the fly: theta_l . u_l
__device__ __forceinline__ float cn_term(float a, float b, int l,
                                         const float4* __restrict__ s_ui4,
                                         const float4* __restrict__ s_uj4,
                                         const float* __restrict__ theta,
                                         const float* __restrict__ emb_t) {
    const float4* th = (const float4*)(theta + (size_t)l * DD);
    const float4* ul = (const float4*)(emb_t + (size_t)l * DD);
    float tl = 0.f, ti = 0.f, tj = 0.f;
    #pragma unroll
    for (int q = 0; q < DD / 4; q++) {
        float4 t = __ldg(th + q);
        float4 u = __ldg(ul + q);
        float4 vi = s_ui4[q];
        float4 vj = s_uj4[q];
        tl += t.x * u.x  + t.y * u.y  + t.z * u.z  + t.w * u.w;
        ti += t.x * vi.x + t.y * vi.y + t.z * vi.z + t.w * vi.w;
        tj += t.x * vj.x + t.y * vj.y + t.z * vj.z + t.w * vj.w;
    }
    float dot = a * (tl - ti) + b * (tl - tj);
    if (dot < -100.f) return 1.f;
    float P = 1.f / (1.f + expf(-dot));
    return 1.f - P;
}

// ONE kernel: [0,SS) L_tr samples FIRST (start DMA asap), then smooth, then hinge.
__global__ void __launch_bounds__(THREADS) fused_kernel(
    const float* __restrict__ emb_t,
    const float* __restrict__ emb_prev,
    const float* __restrict__ theta,
    const float* __restrict__ adj,
    const int* __restrict__ j_idx,
    const int* __restrict__ k_idx,
    const int* __restrict__ negj_idx,
    const int* __restrict__ i_idx,
    const int* __restrict__ cond) {

    extern __shared__ __align__(16) float sbuf[];     // [NBUF][2][CHUNK_F] = 24 KB
    __shared__ alignas(8) unsigned long long smbar[NBUF];
    __shared__ float s_ui[DD];
    __shared__ float s_uj[DD];
    __shared__ float s_red[4];
    __shared__ float s_tik, s_tjk, s_dgk;

    int bid = blockIdx.x;
    int tid = threadIdx.x;
    int lane = tid & 31, w = tid >> 5;

    // ================= smooth: sum (emb_t - emb_prev)^2 =================
    if (bid >= SS && bid < SS + SMOOTH_BLKS) {
        int sb_id = bid - SS;
        const float4* et = (const float4*)emb_t;
        const float4* ep = (const float4*)emb_prev;
        const int TOT4 = NN * DD / 4;                 // 131072
        float ssum = 0.f;
        for (int q = sb_id * THREADS + tid; q < TOT4; q += SMOOTH_BLKS * THREADS) {
            float4 a = __ldg(et + q);
            float4 b = __ldg(ep + q);
            float dx = a.x - b.x, dy = a.y - b.y, dz = a.z - b.z, dw = a.w - b.w;
            ssum += dx * dx + dy * dy + dz * dz + dw * dw;
        }
        #pragma unroll
        for (int o = 16; o; o >>= 1) ssum += __shfl_down_sync(0xffffffffu, ssum, o);
        if (lane == 0) s_red[w] = ssum;
        __syncthreads();
        if (tid == 0) {
            float t = s_red[0] + s_red[1] + s_red[2] + s_red[3];
            atomicAdd(&g_sq, t);
        }
        return;
    }
    // ================= triplet hinge =================
    if (bid >= SS + SMOOTH_BLKS) {
        int s = (bid - SS - SMOOTH_BLKS) * 4 + w;
        int j = j_idx[s], k = k_idx[s], nj = negj_idx[s];
        const float* uj = emb_t + (size_t)j  * DD;
        const float* uk = emb_t + (size_t)k  * DD;
        const float* un = emb_t + (size_t)nj * DD;
        float pos = 0.f, neg = 0.f;
        #pragma unroll
        for (int d = lane; d < DD; d += 32) {
            float a = uj[d] - uk[d]; pos += a * a;
            float b = un[d] - uk[d]; neg += b * b;
        }
        #pragma unroll
        for (int o = 16; o; o >>= 1) {
            pos += __shfl_down_sync(0xffffffffu, pos, o);
            neg += __shfl_down_sync(0xffffffffu, neg, o);
        }
        float h = pos - neg + 1.0f;
        if (lane == 0) s_red[w] = (h > 0.f) ? h : 0.f;
        __syncthreads();
        if (tid == 0) {
            float t = s_red[0] + s_red[1] + s_red[2] + s_red[3];
            if (t != 0.f) atomicAdd(&g_Lsh, t);
        }
        return;
    }
    // ================= L_tr: one block per sample =================
    {
        int s = bid;
        int c = __ldg(cond + s);
        if (c == -1) return;

        int i = __ldg(i_idx + s), j = __ldg(j_idx + s), k = __ldg(k_idx + s);

        if (tid < DD)  s_ui[tid]      = emb_t[(size_t)i * DD + tid];
        else           s_uj[tid - DD] = emb_t[(size_t)j * DD + (tid - DD)];

        uint32_t mb0 = (uint32_t)__cvta_generic_to_shared(&smbar[0]);
        if (c == 1 && tid == 0) {
            #pragma unroll
            for (int cc = 0; cc < NBUF; ++cc) mbar_init(mb0 + 8 * cc, 1);
            asm volatile("fence.proxy.async.shared::cta;" ::: "memory");
        }
        __syncthreads();

        float prodL = 1.f;
        if (c == 1) {
            const float* ri = adj + (size_t)i * NN;
            const float* rj = adj + (size_t)j * NN;
            uint32_t sb = (uint32_t)__cvta_generic_to_shared(sbuf);

            if (tid == 0) {
                #pragma unroll
                for (int cc = 0; cc < NBUF; ++cc) {
                    uint32_t mb = mb0 + 8 * cc;
                    uint32_t dst = sb + (uint32_t)cc * 2 * CHUNK_B;
                    mbar_expect_tx(mb, 2 * CHUNK_B);
                    bulk_g2s(dst,           ri + (size_t)cc * CHUNK_F, CHUNK_B, mb);
                    bulk_g2s(dst + CHUNK_B, rj + (size_t)cc * CHUNK_F, CHUNK_B, mb);
                }
            }
            const float4* s_ui4 = (const float4*)s_ui;
            const float4* s_uj4 = (const float4*)s_uj;

            #pragma unroll
            for (int cc = 0; cc < NCHUNK; ++cc) {
                int buf = cc % NBUF;                   // 0,1,2,0,1,2,0,1
                int ph  = cc / NBUF;                   // 0,0,0,1,1,1,2,2
                mbar_wait(mb0 + 8 * buf, ph & 1);
                const float4* A = (const float4*)(sbuf + (size_t)buf * 2 * CHUNK_F);
                const float4* B = (const float4*)(sbuf + (size_t)buf * 2 * CHUNK_F + CHUNK_F);
                #pragma unroll
                for (int it = 0; it < CHUNK_F / 4 / THREADS; ++it) {   // 2 iterations
                    int q = tid + it * THREADS;
                    float4 a = A[q];
                    float4 b = B[q];
                    int l0 = cc * CHUNK_F + q * 4;
                    if (a.x > 0.f && b.x > 0.f)
                        prodL *= cn_term(a.x, b.x, l0 + 0, s_ui4, s_uj4, theta, emb_t);
                    if (a.y > 0.f && b.y > 0.f)
                        prodL *= cn_term(a.y, b.y, l0 + 1, s_ui4, s_uj4, theta, emb_t);
                    if (a.z > 0.f && b.z > 0.f)
                        prodL *= cn_term(a.z, b.z, l0 + 2, s_ui4, s_uj4, theta, emb_t);
                    if (a.w > 0.f && b.w > 0.f)
                        prodL *= cn_term(a.w, b.w, l0 + 3, s_ui4, s_uj4, theta, emb_t);
                }
                if (cc + NBUF < NCHUNK) {
                    // this buffer fully consumed -> reissue chunk cc+NBUF into it
                    __syncthreads();
                    if (tid == 0) {
                        uint32_t mb = mb0 + 8 * buf;
                        uint32_t dst = sb + (uint32_t)buf * 2 * CHUNK_B;
                        mbar_expect_tx(mb, 2 * CHUNK_B);
                        bulk_g2s(dst,           ri + (size_t)(cc + NBUF) * CHUNK_F, CHUNK_B, mb);
                        bulk_g2s(dst + CHUNK_B, rj + (size_t)(cc + NBUF) * CHUNK_F, CHUNK_B, mb);
                    }
                }
            }
        }

        #pragma unroll
        for (int o = 16; o; o >>= 1)
            prodL *= __shfl_xor_sync(0xffffffffu, prodL, o);
        if (lane == 0) s_red[w] = prodL;
        __syncthreads();

        // warp0: theta_k.u_i ; warp1: theta_k.u_j ; warp2: theta_k.u_k
        if (w < 3) {
            const float* th = theta + (size_t)k * DD;
            const float* u = (w == 0) ? s_ui
                           : (w == 1) ? s_uj
                                      : emb_t + (size_t)k * DD;
            float acc = 0.f;
            #pragma unroll
            for (int d = lane; d < DD; d += 32) acc += u[d] * th[d];
            #pragma unroll
            for (int o = 16; o; o >>= 1)
                acc += __shfl_down_sync(0xffffffffu, acc, o);
            if (lane == 0) {
                if (w == 0) s_tik = acc;
                else if (w == 1) s_tjk = acc;
                else s_dgk = acc;
            }
        }
        __syncthreads();

        if (tid == 0) {
            float prodAll = s_red[0] * s_red[1] * s_red[2] * s_red[3];

            float a_ik = __ldg(adj + (size_t)i * NN + k);
            float a_jk = __ldg(adj + (size_t)j * NN + k);
            float dg = s_dgk;
            float dot_k = a_ik * (dg - s_tik) + a_jk * (dg - s_tjk);

            float ltr = softplus_stable(-dot_k);
            if (c == 1) {
                float C1 = 1.f - prodAll;
                float C0 = (dot_k < -100.f) ? 0.f : 1.f / (1.f + expf(-dot_k));
                ltr += 1.f - C0 / (C1 + EPS_C);
            } else {
                ltr += dot_k;
            }
            atomicAdd(&g_Ltr, ltr);
        }
    }
}

// reads accumulators, writes result, resets accumulators for the next replay
__global__ void final_kernel(float* __restrict__ out) {
    out[0] = g_Lsh + BETA0 * g_Ltr + BETA1 * ((float)SS) * g_sq;
    g_Lsh = 0.f; g_Ltr = 0.f; g_sq = 0.f;
}

extern "C" void kernel_launch(void* const* d_in, const int* in_sizes, int n_in,
                              void* d_out, int out_size) {
    const float* emb_t    = (const float*)d_in[0];
    const float* emb_prev = (const float*)d_in[1];
    const float* theta    = (const float*)d_in[2];
    const float* adj      = (const float*)d_in[3];
    const int*   j_idx    = (const int*)d_in[4];
    const int*   k_idx    = (const int*)d_in[5];
    const int*   negj_idx = (const int*)d_in[6];
    const int*   i_idx    = (const int*)d_in[7];
    const int*   cond     = (const int*)d_in[8];
    float* out = (float*)d_out;

    cudaFuncSetAttribute(fused_kernel,
                         cudaFuncAttributeMaxDynamicSharedMemorySize, DYN_SMEM);

    fused_kernel<<<TOTAL_BLKS, THREADS, DYN_SMEM>>>(
        emb_t, emb_prev, theta, adj, j_idx, k_idx, negj_idx, i_idx, cond);
    final_kernel<<<1, 1>>>(out);
}

// round 16
// speedup vs baseline: 1.5007x; 1.1429x over previous
#include <cuda_runtime.h>
#include <math.h>
#include <stdint.h>

#define NN 8192
#define DD 64
#define SS 4096
#define BETA0 0.1f
#define BETA1 0.1f
#define EPS_C 1e-6f

#define THREADS 128                       // one sample per 128-thread block
#define CHUNK_F 1024                      // floats per chunk per row (4 KB)
#define CHUNK_B (CHUNK_F * 4)
#define NCHUNK (NN / CHUNK_F)             // 8 chunk-pairs
#define NBUF 2                            // 2 buffers -> 16 KB dyn smem -> ~12 CTA/SM
#define DYN_SMEM (NBUF * 2 * CHUNK_B)     // 16 KB

#define SMOOTH_BLKS 128
#define HINGE_BLKS  1024                  // 4 samples per 128-thr block
// grid layout: [0, SS) = L_tr samples ; [SS, SS+128) = smooth ; then hinge
#define TOTAL_BLKS (SS + SMOOTH_BLKS + HINGE_BLKS)

__device__ float g_Lsh;
__device__ float g_Ltr;
__device__ float g_sq;

__device__ __forceinline__ float softplus_stable(float x) {
    return fmaxf(x, 0.f) + log1pf(expf(-fabsf(x)));
}

// ---- TMA bulk-copy + mbarrier helpers ----
__device__ __forceinline__ void mbar_init(uint32_t mbar, uint32_t count) {
    asm volatile("mbarrier.init.shared.b64 [%0], %1;" :: "r"(mbar), "r"(count) : "memory");
}
__device__ __forceinline__ void mbar_expect_tx(uint32_t mbar, uint32_t bytes) {
    asm volatile("mbarrier.arrive.expect_tx.shared.b64 _, [%0], %1;"
                 :: "r"(mbar), "r"(bytes) : "memory");
}
__device__ __forceinline__ void bulk_g2s(uint32_t dst_smem, const void* src_gmem,
                                         uint32_t bytes, uint32_t mbar) {
    asm volatile(
        "cp.async.bulk.shared::cluster.global.mbarrier::complete_tx::bytes "
        "[%0], [%1], %2, [%3];"
        :: "r"(dst_smem), "l"(src_gmem), "r"(bytes), "r"(mbar) : "memory");
}
__device__ __forceinline__ void mbar_wait(uint32_t mbar, uint32_t parity) {
    asm volatile(
        "{\n\t"
        ".reg .pred P1;\n\t"
        "WAIT_LOOP_%=:\n\t"
        "mbarrier.try_wait.parity.acquire.cta.shared::cta.b64 P1, [%0], %1, 0x989680;\n\t"
        "@P1 bra.uni WAIT_DONE_%=;\n\t"
        "bra.uni WAIT_LOOP_%=;\n\t"
        "WAIT_DONE_%=:\n\t"
        "}"
        :: "r"(mbar), "r"(parity) : "memory");
}

// (1 - P) for one common neighbor; diag computed on the fly: theta_l . u_l
// __noinline__ keeps the (rare) 3-dot-product state OUT of the hot scan loop's
// register footprint so the kernel stays below the 12-CTA/SM reg budget.
__device__ __noinline__ float cn_term(float a, float b, int l,
                                      const float4* s_ui4,
                                      const float4* s_uj4,
                                      const float* theta,
                                      const float* emb_t) {
    const float4* th = (const float4*)(theta + (size_t)l * DD);
    const float4* ul = (const float4*)(emb_t + (size_t)l * DD);
    float tl = 0.f, ti = 0.f, tj = 0.f;
    #pragma unroll
    for (int q = 0; q < DD / 4; q++) {
        float4 t = __ldg(th + q);
        float4 u = __ldg(ul + q);
        float4 vi = s_ui4[q];
        float4 vj = s_uj4[q];
        tl += t.x * u.x  + t.y * u.y  + t.z * u.z  + t.w * u.w;
        ti += t.x * vi.x + t.y * vi.y + t.z * vi.z + t.w * vi.w;
        tj += t.x * vj.x + t.y * vj.y + t.z * vj.z + t.w * vj.w;
    }
    float dot = a * (tl - ti) + b * (tl - tj);
    if (dot < -100.f) return 1.f;
    float P = 1.f / (1.f + expf(-dot));
    return 1.f - P;
}

// ONE kernel: [0,SS) L_tr samples FIRST (start DMA asap), then smooth, then hinge.
__global__ void __launch_bounds__(THREADS) fused_kernel(
    const float* __restrict__ emb_t,
    const float* __restrict__ emb_prev,
    const float* __restrict__ theta,
    const float* __restrict__ adj,
    const int* __restrict__ j_idx,
    const int* __restrict__ k_idx,
    const int* __restrict__ negj_idx,
    const int* __restrict__ i_idx,
    const int* __restrict__ cond) {

    extern __shared__ __align__(16) float sbuf[];     // [NBUF][2][CHUNK_F] = 16 KB
    __shared__ alignas(8) unsigned long long smbar[NBUF];
    __shared__ float s_ui[DD];
    __shared__ float s_uj[DD];
    __shared__ float s_red[4];
    __shared__ float s_tik, s_tjk, s_dgk;

    int bid = blockIdx.x;
    int tid = threadIdx.x;
    int lane = tid & 31, w = tid >> 5;

    // ================= smooth: sum (emb_t - emb_prev)^2 =================
    if (bid >= SS && bid < SS + SMOOTH_BLKS) {
        int sb_id = bid - SS;
        const float4* et = (const float4*)emb_t;
        const float4* ep = (const float4*)emb_prev;
        const int TOT4 = NN * DD / 4;                 // 131072
        float ssum = 0.f;
        for (int q = sb_id * THREADS + tid; q < TOT4; q += SMOOTH_BLKS * THREADS) {
            float4 a = __ldg(et + q);
            float4 b = __ldg(ep + q);
            float dx = a.x - b.x, dy = a.y - b.y, dz = a.z - b.z, dw = a.w - b.w;
            ssum += dx * dx + dy * dy + dz * dz + dw * dw;
        }
        #pragma unroll
        for (int o = 16; o; o >>= 1) ssum += __shfl_down_sync(0xffffffffu, ssum, o);
        if (lane == 0) s_red[w] = ssum;
        __syncthreads();
        if (tid == 0) {
            float t = s_red[0] + s_red[1] + s_red[2] + s_red[3];
            atomicAdd(&g_sq, t);
        }
        return;
    }
    // ================= triplet hinge =================
    if (bid >= SS + SMOOTH_BLKS) {
        int s = (bid - SS - SMOOTH_BLKS) * 4 + w;
        int j = j_idx[s], k = k_idx[s], nj = negj_idx[s];
        const float* uj = emb_t + (size_t)j  * DD;
        const float* uk = emb_t + (size_t)k  * DD;
        const float* un = emb_t + (size_t)nj * DD;
        float pos = 0.f, neg = 0.f;
        #pragma unroll
        for (int d = lane; d < DD; d += 32) {
            float a = uj[d] - uk[d]; pos += a * a;
            float b = un[d] - uk[d]; neg += b * b;
        }
        #pragma unroll
        for (int o = 16; o; o >>= 1) {
            pos += __shfl_down_sync(0xffffffffu, pos, o);
            neg += __shfl_down_sync(0xffffffffu, neg, o);
        }
        float h = pos - neg + 1.0f;
        if (lane == 0) s_red[w] = (h > 0.f) ? h : 0.f;
        __syncthreads();
        if (tid == 0) {
            float t = s_red[0] + s_red[1] + s_red[2] + s_red[3];
            if (t != 0.f) atomicAdd(&g_Lsh, t);
        }
        return;
    }
    // ================= L_tr: one block per sample =================
    {
        int s = bid;
        int c = __ldg(cond + s);
        if (c == -1) return;

        int i = __ldg(i_idx + s), j = __ldg(j_idx + s), k = __ldg(k_idx + s);

        if (tid < DD)  s_ui[tid]      = emb_t[(size_t)i * DD + tid];
        else           s_uj[tid - DD] = emb_t[(size_t)j * DD + (tid - DD)];

        uint32_t mb0 = (uint32_t)__cvta_generic_to_shared(&smbar[0]);
        if (c == 1 && tid == 0) {
            #pragma unroll
            for (int cc = 0; cc < NBUF; ++cc) mbar_init(mb0 + 8 * cc, 1);
            asm volatile("fence.proxy.async.shared::cta;" ::: "memory");
        }
        __syncthreads();

        float prodL = 1.f;
        if (c == 1) {
            const float* ri = adj + (size_t)i * NN;
            const float* rj = adj + (size_t)j * NN;
            uint32_t sb = (uint32_t)__cvta_generic_to_shared(sbuf);

            if (tid == 0) {
                #pragma unroll
                for (int cc = 0; cc < NBUF; ++cc) {
                    uint32_t mb = mb0 + 8 * cc;
                    uint32_t dst = sb + (uint32_t)cc * 2 * CHUNK_B;
                    mbar_expect_tx(mb, 2 * CHUNK_B);
                    bulk_g2s(dst,           ri + (size_t)cc * CHUNK_F, CHUNK_B, mb);
                    bulk_g2s(dst + CHUNK_B, rj + (size_t)cc * CHUNK_F, CHUNK_B, mb);
                }
            }
            const float4* s_ui4 = (const float4*)s_ui;
            const float4* s_uj4 = (const float4*)s_uj;

            #pragma unroll
            for (int cc = 0; cc < NCHUNK; ++cc) {
                int buf = cc & 1;                      // 0,1,0,1,...
                int ph  = (cc >> 1) & 1;               // 0,0,1,1,0,0,1,1
                mbar_wait(mb0 + 8 * buf, ph);
                const float4* A = (const float4*)(sbuf + (size_t)buf * 2 * CHUNK_F);
                const float4* B = (const float4*)(sbuf + (size_t)buf * 2 * CHUNK_F + CHUNK_F);
                #pragma unroll
                for (int it = 0; it < CHUNK_F / 4 / THREADS; ++it) {   // 2 iterations
                    int q = tid + it * THREADS;
                    float4 a = A[q];
                    float4 b = B[q];
                    int l0 = cc * CHUNK_F + q * 4;
                    if (a.x > 0.f && b.x > 0.f)
                        prodL *= cn_term(a.x, b.x, l0 + 0, s_ui4, s_uj4, theta, emb_t);
                    if (a.y > 0.f && b.y > 0.f)
                        prodL *= cn_term(a.y, b.y, l0 + 1, s_ui4, s_uj4, theta, emb_t);
                    if (a.z > 0.f && b.z > 0.f)
                        prodL *= cn_term(a.z, b.z, l0 + 2, s_ui4, s_uj4, theta, emb_t);
                    if (a.w > 0.f && b.w > 0.f)
                        prodL *= cn_term(a.w, b.w, l0 + 3, s_ui4, s_uj4, theta, emb_t);
                }
                if (cc + NBUF < NCHUNK) {
                    // this buffer fully consumed -> reissue chunk cc+NBUF into it
                    __syncthreads();
                    if (tid == 0) {
                        uint32_t mb = mb0 + 8 * buf;
                        uint32_t dst = sb + (uint32_t)buf * 2 * CHUNK_B;
                        mbar_expect_tx(mb, 2 * CHUNK_B);
                        bulk_g2s(dst,           ri + (size_t)(cc + NBUF) * CHUNK_F, CHUNK_B, mb);
                        bulk_g2s(dst + CHUNK_B, rj + (size_t)(cc + NBUF) * CHUNK_F, CHUNK_B, mb);
                    }
                }
            }
        }

        #pragma unroll
        for (int o = 16; o; o >>= 1)
            prodL *= __shfl_xor_sync(0xffffffffu, prodL, o);
        if (lane == 0) s_red[w] = prodL;
        __syncthreads();

        // warp0: theta_k.u_i ; warp1: theta_k.u_j ; warp2: theta_k.u_k
        if (w < 3) {
            const float* th = theta + (size_t)k * DD;
            const float* u = (w == 0) ? s_ui
                           : (w == 1) ? s_uj
                                      : emb_t + (size_t)k * DD;
            float acc = 0.f;
            #pragma unroll
            for (int d = lane; d < DD; d += 32) acc += u[d] * th[d];
            #pragma unroll
            for (int o = 16; o; o >>= 1)
                acc += __shfl_down_sync(0xffffffffu, acc, o);
            if (lane == 0) {
                if (w == 0) s_tik = acc;
                else if (w == 1) s_tjk = acc;
                else s_dgk = acc;
            }
        }
        __syncthreads();

        if (tid == 0) {
            float prodAll = s_red[0] * s_red[1] * s_red[2] * s_red[3];

            float a_ik = __ldg(adj + (size_t)i * NN + k);
            float a_jk = __ldg(adj + (size_t)j * NN + k);
            float dg = s_dgk;
            float dot_k = a_ik * (dg - s_tik) + a_jk * (dg - s_tjk);

            float ltr = softplus_stable(-dot_k);
            if (c == 1) {
                float C1 = 1.f - prodAll;
                float C0 = (dot_k < -100.f) ? 0.f : 1.f / (1.f + expf(-dot_k));
                ltr += 1.f - C0 / (C1 + EPS_C);
            } else {
                ltr += dot_k;
            }
            atomicAdd(&g_Ltr, ltr);
        }
    }
}

// reads accumulators, writes result, resets accumulators for the next replay
__global__ void final_kernel(float* __restrict__ out) {
    out[0] = g_Lsh + BETA0 * g_Ltr + BETA1 * ((float)SS) * g_sq;
    g_Lsh = 0.f; g_Ltr = 0.f; g_sq = 0.f;
}

extern "C" void kernel_launch(void* const* d_in, const int* in_sizes, int n_in,
                              void* d_out, int out_size) {
    const float* emb_t    = (const float*)d_in[0];
    const float* emb_prev = (const float*)d_in[1];
    const float* theta    = (const float*)d_in[2];
    const float* adj      = (const float*)d_in[3];
    const int*   j_idx    = (const int*)d_in[4];
    const int*   k_idx    = (const int*)d_in[5];
    const int*   negj_idx = (const int*)d_in[6];
    const int*   i_idx    = (const int*)d_in[7];
    const int*   cond     = (const int*)d_in[8];
    float* out = (float*)d_out;

    cudaFuncSetAttribute(fused_kernel,
                         cudaFuncAttributeMaxDynamicSharedMemorySize, DYN_SMEM);

    fused_kernel<<<TOTAL_BLKS, THREADS, DYN_SMEM>>>(
        emb_t, emb_prev, theta, adj, j_idx, k_idx, negj_idx, i_idx, cond);
    final_kernel<<<1, 1>>>(out);
}

// round 17
// speedup vs baseline: 1.5686x; 1.0452x over previous
#include <cuda_runtime.h>
#include <math.h>
#include <stdint.h>

#define NN 8192
#define DD 64
#define SS 4096
#define BETA0 0.1f
#define BETA1 0.1f
#define EPS_C 1e-6f

#define THREADS 64                        // one sample per 64-thread block
#define CHUNK_F 512                       // floats per chunk per row (2 KB)
#define CHUNK_B (CHUNK_F * 4)
#define NCHUNK (NN / CHUNK_F)             // 16 chunk-pairs
#define NBUF 2                            // 2 buffers -> 8 KB dyn smem -> ~25 CTA/SM
#define DYN_SMEM (NBUF * 2 * CHUNK_B)     // 8 KB

#define SMOOTH_BLKS 128
#define HINGE_BLKS  2048                  // 2 samples per 64-thr block
// grid layout: [0, SS) = L_tr samples ; [SS, SS+128) = smooth ; then hinge
#define TOTAL_BLKS (SS + SMOOTH_BLKS + HINGE_BLKS)

__device__ float g_Lsh;
__device__ float g_Ltr;
__device__ float g_sq;

__device__ __forceinline__ float softplus_stable(float x) {
    return fmaxf(x, 0.f) + log1pf(expf(-fabsf(x)));
}

// ---- TMA bulk-copy + mbarrier helpers ----
__device__ __forceinline__ void mbar_init(uint32_t mbar, uint32_t count) {
    asm volatile("mbarrier.init.shared.b64 [%0], %1;" :: "r"(mbar), "r"(count) : "memory");
}
__device__ __forceinline__ void mbar_expect_tx(uint32_t mbar, uint32_t bytes) {
    asm volatile("mbarrier.arrive.expect_tx.shared.b64 _, [%0], %1;"
                 :: "r"(mbar), "r"(bytes) : "memory");
}
__device__ __forceinline__ void bulk_g2s(uint32_t dst_smem, const void* src_gmem,
                                         uint32_t bytes, uint32_t mbar) {
    asm volatile(
        "cp.async.bulk.shared::cluster.global.mbarrier::complete_tx::bytes "
        "[%0], [%1], %2, [%3];"
        :: "r"(dst_smem), "l"(src_gmem), "r"(bytes), "r"(mbar) : "memory");
}
__device__ __forceinline__ void mbar_wait(uint32_t mbar, uint32_t parity) {
    asm volatile(
        "{\n\t"
        ".reg .pred P1;\n\t"
        "WAIT_LOOP_%=:\n\t"
        "mbarrier.try_wait.parity.acquire.cta.shared::cta.b64 P1, [%0], %1, 0x989680;\n\t"
        "@P1 bra.uni WAIT_DONE_%=;\n\t"
        "bra.uni WAIT_LOOP_%=;\n\t"
        "WAIT_DONE_%=:\n\t"
        "}"
        :: "r"(mbar), "r"(parity) : "memory");
}

// (1 - P) for one common neighbor; diag computed on the fly: theta_l . u_l
// __noinline__ keeps the (rare) 3-dot-product state OUT of the hot scan loop's
// register footprint so the kernel keeps high occupancy.
__device__ __noinline__ float cn_term(float a, float b, int l,
                                      const float4* s_ui4,
                                      const float4* s_uj4,
                                      const float* theta,
                                      const float* emb_t) {
    const float4* th = (const float4*)(theta + (size_t)l * DD);
    const float4* ul = (const float4*)(emb_t + (size_t)l * DD);
    float tl = 0.f, ti = 0.f, tj = 0.f;
    #pragma unroll
    for (int q = 0; q < DD / 4; q++) {
        float4 t = __ldg(th + q);
        float4 u = __ldg(ul + q);
        float4 vi = s_ui4[q];
        float4 vj = s_uj4[q];
        tl += t.x * u.x  + t.y * u.y  + t.z * u.z  + t.w * u.w;
        ti += t.x * vi.x + t.y * vi.y + t.z * vi.z + t.w * vi.w;
        tj += t.x * vj.x + t.y * vj.y + t.z * vj.z + t.w * vj.w;
    }
    float dot = a * (tl - ti) + b * (tl - tj);
    if (dot < -100.f) return 1.f;
    float P = 1.f / (1.f + expf(-dot));
    return 1.f - P;
}

// ONE kernel: [0,SS) L_tr samples FIRST (start DMA asap), then smooth, then hinge.
__global__ void __launch_bounds__(THREADS) fused_kernel(
    const float* __restrict__ emb_t,
    const float* __restrict__ emb_prev,
    const float* __restrict__ theta,
    const float* __restrict__ adj,
    const int* __restrict__ j_idx,
    const int* __restrict__ k_idx,
    const int* __restrict__ negj_idx,
    const int* __restrict__ i_idx,
    const int* __restrict__ cond) {

    extern __shared__ __align__(16) float sbuf[];     // [NBUF][2][CHUNK_F] = 8 KB
    __shared__ alignas(8) unsigned long long smbar[NBUF];
    __shared__ float s_ui[DD];
    __shared__ float s_uj[DD];
    __shared__ float s_red[2];
    __shared__ float s_tik, s_tjk, s_dgk;

    int bid = blockIdx.x;
    int tid = threadIdx.x;
    int lane = tid & 31, w = tid >> 5;

    // ================= smooth: sum (emb_t - emb_prev)^2 =================
    if (bid >= SS && bid < SS + SMOOTH_BLKS) {
        int sb_id = bid - SS;
        const float4* et = (const float4*)emb_t;
        const float4* ep = (const float4*)emb_prev;
        const int TOT4 = NN * DD / 4;                 // 131072
        float ssum = 0.f;
        for (int q = sb_id * THREADS + tid; q < TOT4; q += SMOOTH_BLKS * THREADS) {
            float4 a = __ldg(et + q);
            float4 b = __ldg(ep + q);
            float dx = a.x - b.x, dy = a.y - b.y, dz = a.z - b.z, dw = a.w - b.w;
            ssum += dx * dx + dy * dy + dz * dz + dw * dw;
        }
        #pragma unroll
        for (int o = 16; o; o >>= 1) ssum += __shfl_down_sync(0xffffffffu, ssum, o);
        if (lane == 0) s_red[w] = ssum;
        __syncthreads();
        if (tid == 0) atomicAdd(&g_sq, s_red[0] + s_red[1]);
        return;
    }
    // ================= triplet hinge: 2 samples per block =================
    if (bid >= SS + SMOOTH_BLKS) {
        int s = (bid - SS - SMOOTH_BLKS) * 2 + w;
        int j = j_idx[s], k = k_idx[s], nj = negj_idx[s];
        const float* uj = emb_t + (size_t)j  * DD;
        const float* uk = emb_t + (size_t)k  * DD;
        const float* un = emb_t + (size_t)nj * DD;
        float pos = 0.f, neg = 0.f;
        #pragma unroll
        for (int d = lane; d < DD; d += 32) {
            float a = uj[d] - uk[d]; pos += a * a;
            float b = un[d] - uk[d]; neg += b * b;
        }
        #pragma unroll
        for (int o = 16; o; o >>= 1) {
            pos += __shfl_down_sync(0xffffffffu, pos, o);
            neg += __shfl_down_sync(0xffffffffu, neg, o);
        }
        float h = pos - neg + 1.0f;
        if (lane == 0) s_red[w] = (h > 0.f) ? h : 0.f;
        __syncthreads();
        if (tid == 0) {
            float t = s_red[0] + s_red[1];
            if (t != 0.f) atomicAdd(&g_Lsh, t);
        }
        return;
    }
    // ================= L_tr: one block per sample =================
    {
        int s = bid;
        int c = __ldg(cond + s);
        if (c == -1) return;

        int i = __ldg(i_idx + s), j = __ldg(j_idx + s), k = __ldg(k_idx + s);

        // 64 threads: each loads one element of each embedding row
        s_ui[tid] = emb_t[(size_t)i * DD + tid];
        s_uj[tid] = emb_t[(size_t)j * DD + tid];

        uint32_t mb0 = (uint32_t)__cvta_generic_to_shared(&smbar[0]);
        if (c == 1 && tid == 0) {
            #pragma unroll
            for (int cc = 0; cc < NBUF; ++cc) mbar_init(mb0 + 8 * cc, 1);
            asm volatile("fence.proxy.async.shared::cta;" ::: "memory");
        }
        __syncthreads();

        float prodL = 1.f;
        if (c == 1) {
            const float* ri = adj + (size_t)i * NN;
            const float* rj = adj + (size_t)j * NN;
            uint32_t sb = (uint32_t)__cvta_generic_to_shared(sbuf);

            if (tid == 0) {
                #pragma unroll
                for (int cc = 0; cc < NBUF; ++cc) {
                    uint32_t mb = mb0 + 8 * cc;
                    uint32_t dst = sb + (uint32_t)cc * 2 * CHUNK_B;
                    mbar_expect_tx(mb, 2 * CHUNK_B);
                    bulk_g2s(dst,           ri + (size_t)cc * CHUNK_F, CHUNK_B, mb);
                    bulk_g2s(dst + CHUNK_B, rj + (size_t)cc * CHUNK_F, CHUNK_B, mb);
                }
            }
            const float4* s_ui4 = (const float4*)s_ui;
            const float4* s_uj4 = (const float4*)s_uj;

            #pragma unroll
            for (int cc = 0; cc < NCHUNK; ++cc) {
                int buf = cc & 1;                      // 0,1,0,1,...
                int ph  = (cc >> 1) & 1;               // parity flips each reuse
                mbar_wait(mb0 + 8 * buf, ph);
                const float4* A = (const float4*)(sbuf + (size_t)buf * 2 * CHUNK_F);
                const float4* B = (const float4*)(sbuf + (size_t)buf * 2 * CHUNK_F + CHUNK_F);
                #pragma unroll
                for (int it = 0; it < CHUNK_F / 4 / THREADS; ++it) {   // 2 iterations
                    int q = tid + it * THREADS;
                    float4 a = A[q];
                    float4 b = B[q];
                    int l0 = cc * CHUNK_F + q * 4;
                    if (a.x > 0.f && b.x > 0.f)
                        prodL *= cn_term(a.x, b.x, l0 + 0, s_ui4, s_uj4, theta, emb_t);
                    if (a.y > 0.f && b.y > 0.f)
                        prodL *= cn_term(a.y, b.y, l0 + 1, s_ui4, s_uj4, theta, emb_t);
                    if (a.z > 0.f && b.z > 0.f)
                        prodL *= cn_term(a.z, b.z, l0 + 2, s_ui4, s_uj4, theta, emb_t);
                    if (a.w > 0.f && b.w > 0.f)
                        prodL *= cn_term(a.w, b.w, l0 + 3, s_ui4, s_uj4, theta, emb_t);
                }
                if (cc + NBUF < NCHUNK) {
                    // this buffer fully consumed -> reissue chunk cc+NBUF into it
                    __syncthreads();
                    if (tid == 0) {
                        uint32_t mb = mb0 + 8 * buf;
                        uint32_t dst = sb + (uint32_t)buf * 2 * CHUNK_B;
                        mbar_expect_tx(mb, 2 * CHUNK_B);
                        bulk_g2s(dst,           ri + (size_t)(cc + NBUF) * CHUNK_F, CHUNK_B, mb);
                        bulk_g2s(dst + CHUNK_B, rj + (size_t)(cc + NBUF) * CHUNK_F, CHUNK_B, mb);
                    }
                }
            }
        }

        #pragma unroll
        for (int o = 16; o; o >>= 1)
            prodL *= __shfl_xor_sync(0xffffffffu, prodL, o);
        if (lane == 0) s_red[w] = prodL;
        __syncthreads();

        // warp0: theta_k.u_i then theta_k.u_k ; warp1: theta_k.u_j
        {
            const float* th = theta + (size_t)k * DD;
            const float* u1 = (w == 0) ? s_ui : s_uj;
            float acc = 0.f;
            #pragma unroll
            for (int d = lane; d < DD; d += 32) acc += u1[d] * th[d];
            #pragma unroll
            for (int o = 16; o; o >>= 1)
                acc += __shfl_down_sync(0xffffffffu, acc, o);
            if (lane == 0) { if (w == 0) s_tik = acc; else s_tjk = acc; }

            if (w == 0) {
                const float* uk = emb_t + (size_t)k * DD;
                float acc2 = 0.f;
                #pragma unroll
                for (int d = lane; d < DD; d += 32) acc2 += uk[d] * th[d];
                #pragma unroll
                for (int o = 16; o; o >>= 1)
                    acc2 += __shfl_down_sync(0xffffffffu, acc2, o);
                if (lane == 0) s_dgk = acc2;
            }
        }
        __syncthreads();

        if (tid == 0) {
            float prodAll = s_red[0] * s_red[1];

            float a_ik = __ldg(adj + (size_t)i * NN + k);
            float a_jk = __ldg(adj + (size_t)j * NN + k);
            float dg = s_dgk;
            float dot_k = a_ik * (dg - s_tik) + a_jk * (dg - s_tjk);

            float ltr = softplus_stable(-dot_k);
            if (c == 1) {
                float C1 = 1.f - prodAll;
                float C0 = (dot_k < -100.f) ? 0.f : 1.f / (1.f + expf(-dot_k));
                ltr += 1.f - C0 / (C1 + EPS_C);
            } else {
                ltr += dot_k;
            }
            atomicAdd(&g_Ltr, ltr);
        }
    }
}

// reads accumulators, writes result, resets accumulators for the next replay
__global__ void final_kernel(float* __restrict__ out) {
    out[0] = g_Lsh + BETA0 * g_Ltr + BETA1 * ((float)SS) * g_sq;
    g_Lsh = 0.f; g_Ltr = 0.f; g_sq = 0.f;
}

extern "C" void kernel_launch(void* const* d_in, const int* in_sizes, int n_in,
                              void* d_out, int out_size) {
    const float* emb_t    = (const float*)d_in[0];
    const float* emb_prev = (const float*)d_in[1];
    const float* theta    = (const float*)d_in[2];
    const float* adj      = (const float*)d_in[3];
    const int*   j_idx    = (const int*)d_in[4];
    const int*   k_idx    = (const int*)d_in[5];
    const int*   negj_idx = (const int*)d_in[6];
    const int*   i_idx    = (const int*)d_in[7];
    const int*   cond     = (const int*)d_in[8];
    float* out = (float*)d_out;

    cudaFuncSetAttribute(fused_kernel,
                         cudaFuncAttributeMaxDynamicSharedMemorySize, DYN_SMEM);

    fused_kernel<<<TOTAL_BLKS, THREADS, DYN_SMEM>>>(
        emb_t, emb_prev, theta, adj, j_idx, k_idx, negj_idx, i_idx, cond);
    final_kernel<<<1, 1>>>(out);
}